// round 15
// baseline (speedup 1.0000x reference)
#include <cuda_runtime.h>
#include <math.h>

#define NATOMS 256
#define RCR 5.2f
#define RCA 3.5f
#define PI_F 3.14159265358979323846f
#define FULL 0xFFFFFFFFu
#define TPB 128    // 4 warps per atom
#define NREP (NATOMS / TPB)   // 2

typedef unsigned long long u64;
#define PACK2(o, lo, hi) asm("mov.b64 %0, {%1, %2};" : "=l"(o) : "f"(lo), "f"(hi))
#define UNPACK2(lo, hi, in) asm("mov.b64 {%0, %1}, %2;" : "=f"(lo), "=f"(hi) : "l"(in))
#define MUL2(o, a, b) asm("mul.rn.f32x2 %0, %1, %2;" : "=l"(o) : "l"(a), "l"(b))
#define FMA2(o, a, b, c) asm("fma.rn.f32x2 %0, %1, %2, %3;" : "=l"(o) : "l"(a), "l"(b), "l"(c))

// radial Gaussian recurrence: S = exp(-2*EtaR*dR^2) = exp(-2.31125)
#define RS_P4  9.65934e-5f
#define RS_P5  9.57601e-6f
#define RS_P6  9.49340e-7f
#define RS_P12 9.01244e-13f
#define RS_P13 8.93468e-14f
#define RS_P14 8.85760e-15f
#define RS_M1  10.087026f
#define RS_M2  101.74809f
#define RS_M3  1026.3357f
#define RS_M8  1.071779e8f
#define RS_M9  1.081106e9f
#define RS_M10 1.090515e10f
#define RS_M11 1.100005e11f
// angular: S_A = exp(-2*EtaA*dA^2) = exp(-6.76)
#define SA1 1.159227e-3f
#define SA2 1.343810e-6f

__global__ void __launch_bounds__(TPB) aev_kernel(
    const float* __restrict__ coords,
    const float* __restrict__ charges,
    float* __restrict__ out)
{
    __shared__ float rd[96], rw[96];                          // radial: dist, 0.25*fc*q
    __shared__ float aux[48], auy[48], auz[48];               // angular: UNIT i->j vector
    __shared__ float ad[48], afq[48];                         // dist, fc*q
    __shared__ int   wcR[NREP * 4], wcA[NREP * 4];            // per (rep,warp) counts
    __shared__ float part[TPB][49];                           // padded transpose buffer

    const int i    = blockIdx.x;
    const int tid  = threadIdx.x;
    const int w    = tid >> 5;
    const int lane = tid & 31;
    const unsigned below = (1u << lane) - 1u;

    const float xi = __ldg(&coords[i * 3 + 0]);
    const float yi = __ldg(&coords[i * 3 + 1]);
    const float zi = __ldg(&coords[i * 3 + 2]);

    // ---------- pass 1: distances + ballots (deterministic ordering) ----------
    float dxv[NREP], dyv[NREP], dzv[NREP], dv[NREP], qv[NREP];
    unsigned mRv[NREP], mAv[NREP];
    bool inRv[NREP], inAv[NREP];

    #pragma unroll
    for (int rep = 0; rep < NREP; rep++) {
        const int j = rep * TPB + tid;
        const float dx = __ldg(&coords[j * 3 + 0]) - xi;
        const float dy = __ldg(&coords[j * 3 + 1]) - yi;
        const float dz = __ldg(&coords[j * 3 + 2]) - zi;
        const float d  = sqrtf(dx * dx + dy * dy + dz * dz);
        const bool ok  = (j != i);
        const bool inR = ok && (d < RCR);
        const bool inA = ok && (d < RCA);
        dxv[rep] = dx; dyv[rep] = dy; dzv[rep] = dz; dv[rep] = d;
        qv[rep]  = __ldg(&charges[j]);
        inRv[rep] = inR; inAv[rep] = inA;
        mRv[rep] = __ballot_sync(FULL, inR);
        mAv[rep] = __ballot_sync(FULL, inA);
        if (lane == 0) {
            wcR[rep * 4 + w] = __popc(mRv[rep]);
            wcA[rep * 4 + w] = __popc(mAv[rep]);
        }
    }
    __syncthreads();

    // ---------- pass 2: compaction; normalize vectors + fold cutoffs here ----------
    #pragma unroll
    for (int rep = 0; rep < NREP; rep++) {
        const int seg = rep * 4 + w;
        int baseR = 0, baseA = 0;
        #pragma unroll
        for (int k = 0; k < NREP * 4; k++)
            if (k < seg) { baseR += wcR[k]; baseA += wcA[k]; }
        if (inRv[rep]) {
            const int s = baseR + __popc(mRv[rep] & below);
            const float d  = dv[rep];
            const float fc = 0.5f * __cosf((PI_F / RCR) * d) + 0.5f;
            rd[s] = d; rw[s] = 0.25f * fc * qv[rep];
        }
        if (inAv[rep]) {
            const int s = baseA + __popc(mAv[rep] & below);
            const float d    = dv[rep];
            const float rinv = __frcp_rn(d);
            const float fc   = 0.5f * __cosf((PI_F / RCA) * d) + 0.5f;
            aux[s] = dxv[rep] * rinv; auy[s] = dyv[rep] * rinv; auz[s] = dzv[rep] * rinv;
            ad[s] = d; afq[s] = fc * qv[rep];
        }
    }
    __syncthreads();

    int NR = 0, NA = 0;
    #pragma unroll
    for (int k = 0; k < NREP * 4; k++) { NR += wcR[k]; NA += wcA[k]; }

    // ---------- radial: neighbor-per-lane, Gaussian recurrence (4 MUFU) ----------
    u64 accR2[8];
    #pragma unroll
    for (int s = 0; s < 8; s++) accR2[s] = 0ull;

    u64 KA0, KA1, KA2, KD0, KD1, KD2, KD3;
    PACK2(KA0, RS_P4, RS_P12);
    PACK2(KA1, RS_P5, RS_P13);
    PACK2(KA2, RS_P6, RS_P14);
    PACK2(KD0, RS_M3, RS_M11);
    PACK2(KD1, RS_M2, RS_M10);
    PACK2(KD2, RS_M1, RS_M9);
    PACK2(KD3, 1.0f,  RS_M8);

    for (int t = tid; t < NR; t += TPB) {
        const float d  = rd[t];
        const float wq = rw[t];
        const float u4  = d - 1.975f;
        const float u12 = d - 4.125f;
        const float g4   = __expf(-16.0f * u4 * u4);
        const float g12  = __expf(-16.0f * u12 * u12);
        const float R    = __expf(8.6f * d - 8.895625f);
        const float Rinv = __expf(8.895625f - 8.6f * d);
        u64 E2, R2, RI2, WQ2;
        PACK2(E2, g4, g12);
        PACK2(R2, R, R);
        PACK2(RI2, Rinv, Rinv);
        PACK2(WQ2, wq, wq);
        FMA2(accR2[4], WQ2, E2, accR2[4]);
        u64 A2 = E2;
        MUL2(A2, A2, R2);  MUL2(A2, A2, KA0); FMA2(accR2[5], WQ2, A2, accR2[5]);
        MUL2(A2, A2, R2);  MUL2(A2, A2, KA1); FMA2(accR2[6], WQ2, A2, accR2[6]);
        MUL2(A2, A2, R2);  MUL2(A2, A2, KA2); FMA2(accR2[7], WQ2, A2, accR2[7]);
        u64 D2 = E2;
        MUL2(D2, D2, RI2); MUL2(D2, D2, KD0); FMA2(accR2[3], WQ2, D2, accR2[3]);
        MUL2(D2, D2, RI2); MUL2(D2, D2, KD1); FMA2(accR2[2], WQ2, D2, accR2[2]);
        MUL2(D2, D2, RI2); MUL2(D2, D2, KD2); FMA2(accR2[1], WQ2, D2, accR2[1]);
        MUL2(D2, D2, RI2); MUL2(D2, D2, KD3); FMA2(accR2[0], WQ2, D2, accR2[0]);
    }

    // ---------- angular: triangular pair-per-lane, unit vectors, f32x2 slots ----------
    u64 CZ2[4], SZ2[4], HALF2;
    PACK2(CZ2[0],  0.49039264f,  0.41573481f);
    PACK2(CZ2[1],  0.27778512f,  0.09754516f);
    PACK2(CZ2[2], -0.09754516f, -0.27778512f);
    PACK2(CZ2[3], -0.41573481f, -0.49039264f);
    PACK2(SZ2[0],  0.09754516f,  0.27778512f);
    PACK2(SZ2[1],  0.41573481f,  0.49039264f);
    PACK2(SZ2[2],  0.49039264f,  0.41573481f);
    PACK2(SZ2[3],  0.27778512f,  0.09754516f);
    PACK2(HALF2, 0.5f, 0.5f);

    u64 accA2[16];
    #pragma unroll
    for (int s = 0; s < 16; s++) accA2[s] = 0ull;

    const int M   = NA;
    const int PPh = (M * (M - 1)) >> 1;   // unordered pairs; ref double-counts -> x2 in wgt
    for (int k = tid; k < PPh; k += TPB) {
        // decode triangular index: k = b(b-1)/2 + a, 0 <= a < b
        int b = (int)(0.5f * (1.0f + sqrtf(8.0f * (float)k + 1.0f)));
        int tb = (b * (b - 1)) >> 1;
        if (k < tb)           { b--; tb = (b * (b - 1)) >> 1; }
        else if (k >= tb + b) { b++; tb = (b * (b - 1)) >> 1; }
        const int a = k - tb;

        // unit-vector dot: no divide in the chain
        const float cth = 0.95f * (aux[a] * aux[b] + auy[a] * auy[b] + auz[a] * auz[b]);
        const float sth = sqrtf(fmaxf(1.0f - cth * cth, 0.0f));  // theta in [0,pi]
        const float wgt = 2.0f * afq[a] * afq[b];
        const float davg = 0.5f * (ad[a] + ad[b]);

        // Gaussian recurrence over the 4 ShfA shifts (2 MUFU)
        const float u0 = davg - 0.9f;
        const float G0 = __expf(-8.0f * u0 * u0);
        const float RA = __expf(10.4f * davg - 12.74f);
        float Gm[4];
        Gm[0] = G0;
        Gm[1] = Gm[0] * RA;
        Gm[2] = Gm[1] * (RA * SA1);
        Gm[3] = Gm[2] * (RA * SA2);

        u64 cth2, sth2;
        PACK2(cth2, cth, cth);
        PACK2(sth2, sth, sth);

        #pragma unroll
        for (int az = 0; az < 4; az++) {
            const float rad = wgt * Gm[az];
            u64 rad2;
            PACK2(rad2, rad, rad);
            #pragma unroll
            for (int p = 0; p < 4; p++) {
                // x = 0.5 + cth*0.5cos(ShfZ) + sth*0.5sin(ShfZ)
                u64 x, t;
                FMA2(t, sth2, SZ2[p], HALF2);
                FMA2(x, cth2, CZ2[p], t);
                MUL2(x, x, x);   // x^2
                MUL2(x, x, x);   // x^4
                MUL2(x, x, x);   // x^8
                MUL2(x, x, x);   // x^16
                MUL2(x, x, x);   // x^32
                FMA2(accA2[az * 4 + p], rad2, x, accA2[az * 4 + p]);
            }
        }
    }

    // ---------- shared transpose ----------
    #pragma unroll
    for (int s = 0; s < 8; s++) {
        float lo, hi;
        UNPACK2(lo, hi, accR2[s]);
        part[tid][s]     = lo;   // slot m = s
        part[tid][s + 8] = hi;   // slot m = s + 8
    }
    #pragma unroll
    for (int s = 0; s < 16; s++) {
        float lo, hi;
        UNPACK2(lo, hi, accA2[s]);
        part[tid][16 + 2 * s]     = lo;
        part[tid][16 + 2 * s + 1] = hi;
    }
    __syncthreads();

    // ---------- bounded 8-way-ILP column sums ----------
    if (tid < 48) {
        const int rawB = (tid < 16) ? NR : PPh;
        const int bnd  = (min(rawB, TPB) + 7) & ~7;
        float v0 = 0.f, v1 = 0.f, v2 = 0.f, v3 = 0.f;
        float v4 = 0.f, v5 = 0.f, v6 = 0.f, v7 = 0.f;
        for (int l = 0; l < bnd; l += 8) {
            v0 += part[l + 0][tid];
            v1 += part[l + 1][tid];
            v2 += part[l + 2][tid];
            v3 += part[l + 3][tid];
            v4 += part[l + 4][tid];
            v5 += part[l + 5][tid];
            v6 += part[l + 6][tid];
            v7 += part[l + 7][tid];
        }
        out[i * 48 + tid] = ((v0 + v1) + (v2 + v3)) + ((v4 + v5) + (v6 + v7));
    }
}

extern "C" void kernel_launch(void* const* d_in, const int* in_sizes, int n_in,
                              void* d_out, int out_size) {
    const float* coords  = (const float*)d_in[0];  // [256,3] fp32
    const float* charges = (const float*)d_in[1];  // [256]   fp32
    float* out = (float*)d_out;                    // [256,48] fp32
    aev_kernel<<<NATOMS, TPB>>>(coords, charges, out);
}

// round 17
// speedup vs baseline: 1.0891x; 1.0891x over previous
#include <cuda_runtime.h>
#include <math.h>

#define NATOMS 256
#define RCR 5.2f
#define RCA 3.5f
#define PI_F 3.14159265358979323846f
#define FULL 0xFFFFFFFFu
#define TPB 128    // 4 warps per atom
#define NREP (NATOMS / TPB)   // 2

typedef unsigned long long u64;
#define PACK2(o, lo, hi) asm("mov.b64 %0, {%1, %2};" : "=l"(o) : "f"(lo), "f"(hi))
#define UNPACK2(lo, hi, in) asm("mov.b64 {%0, %1}, %2;" : "=f"(lo), "=f"(hi) : "l"(in))
#define MUL2(o, a, b) asm("mul.rn.f32x2 %0, %1, %2;" : "=l"(o) : "l"(a), "l"(b))
#define FMA2(o, a, b, c) asm("fma.rn.f32x2 %0, %1, %2, %3;" : "=l"(o) : "l"(a), "l"(b), "l"(c))

__global__ void __launch_bounds__(TPB) aev_kernel(
    const float* __restrict__ coords,
    const float* __restrict__ charges,
    float* __restrict__ out)
{
    __shared__ float rd[96], rw[96];                          // radial: dist, 0.25*fc*q
    __shared__ float adx[48], ady[48], adz[48];               // angular: i->j vector
    __shared__ float ad[48], afq[48];                         // dist, fc*q
    __shared__ int   wcR[NREP * 4], wcA[NREP * 4];            // per (rep,warp) counts
    __shared__ float part[TPB][49];                           // padded transpose buffer

    const int i    = blockIdx.x;
    const int tid  = threadIdx.x;
    const int w    = tid >> 5;
    const int lane = tid & 31;
    const unsigned below = (1u << lane) - 1u;

    const float xi = __ldg(&coords[i * 3 + 0]);
    const float yi = __ldg(&coords[i * 3 + 1]);
    const float zi = __ldg(&coords[i * 3 + 2]);

    // ---------- pass 1: distances + ballots (deterministic ordering) ----------
    float dxv[NREP], dyv[NREP], dzv[NREP], dv[NREP], qv[NREP];
    unsigned mRv[NREP], mAv[NREP];
    bool inRv[NREP], inAv[NREP];

    #pragma unroll
    for (int rep = 0; rep < NREP; rep++) {
        const int j = rep * TPB + tid;
        const float dx = __ldg(&coords[j * 3 + 0]) - xi;
        const float dy = __ldg(&coords[j * 3 + 1]) - yi;
        const float dz = __ldg(&coords[j * 3 + 2]) - zi;
        const float d  = sqrtf(dx * dx + dy * dy + dz * dz);
        const bool ok  = (j != i);
        const bool inR = ok && (d < RCR);
        const bool inA = ok && (d < RCA);
        dxv[rep] = dx; dyv[rep] = dy; dzv[rep] = dz; dv[rep] = d;
        qv[rep]  = __ldg(&charges[j]);
        inRv[rep] = inR; inAv[rep] = inA;
        mRv[rep] = __ballot_sync(FULL, inR);
        mAv[rep] = __ballot_sync(FULL, inA);
        if (lane == 0) {
            wcR[rep * 4 + w] = __popc(mRv[rep]);
            wcA[rep * 4 + w] = __popc(mAv[rep]);
        }
    }
    __syncthreads();

    // ---------- pass 2: exclusive-prefix bases + compacted writes (+fc math) ----------
    #pragma unroll
    for (int rep = 0; rep < NREP; rep++) {
        const int seg = rep * 4 + w;
        int baseR = 0, baseA = 0;
        #pragma unroll
        for (int k = 0; k < NREP * 4; k++)
            if (k < seg) { baseR += wcR[k]; baseA += wcA[k]; }
        if (inRv[rep]) {
            const int s = baseR + __popc(mRv[rep] & below);
            const float d  = dv[rep];
            const float fc = 0.5f * __cosf((PI_F / RCR) * d) + 0.5f;
            rd[s] = d; rw[s] = 0.25f * fc * qv[rep];
        }
        if (inAv[rep]) {
            const int s = baseA + __popc(mAv[rep] & below);
            const float d  = dv[rep];
            const float fc = 0.5f * __cosf((PI_F / RCA) * d) + 0.5f;
            adx[s] = dxv[rep]; ady[s] = dyv[rep]; adz[s] = dzv[rep];
            ad[s] = d; afq[s] = fc * qv[rep];
        }
    }
    __syncthreads();

    int NR = 0, NA = 0;
    #pragma unroll
    for (int k = 0; k < NREP * 4; k++) { NR += wcR[k]; NA += wcA[k]; }

    // ---------- radial: neighbor-per-lane, 16 slots serial (high ILP) ----------
    float accR[16];
    #pragma unroll
    for (int m = 0; m < 16; m++) accR[m] = 0.0f;

    for (int t = tid; t < NR; t += TPB) {
        const float d  = rd[t];
        const float wq = rw[t];
        #pragma unroll
        for (int m = 0; m < 16; m++) {
            const float sh = 0.9f + 0.26875f * (float)m;
            const float u  = d - sh;
            accR[m] += wq * __expf(-16.0f * u * u);
        }
    }

    // ---------- angular: triangular pair-per-lane, packed f32x2 slot math ----------
    // 0.5*cos(ShfZ) / 0.5*sin(ShfZ) for ShfZ = pi/16 + (pi/8)*z, z = 0..7,
    // packed in (z, z+1) pairs.
    u64 CZ2[4], SZ2[4], HALF2;
    PACK2(CZ2[0],  0.49039264f,  0.41573481f);
    PACK2(CZ2[1],  0.27778512f,  0.09754516f);
    PACK2(CZ2[2], -0.09754516f, -0.27778512f);
    PACK2(CZ2[3], -0.41573481f, -0.49039264f);
    PACK2(SZ2[0],  0.09754516f,  0.27778512f);
    PACK2(SZ2[1],  0.41573481f,  0.49039264f);
    PACK2(SZ2[2],  0.49039264f,  0.41573481f);
    PACK2(SZ2[3],  0.27778512f,  0.09754516f);
    PACK2(HALF2, 0.5f, 0.5f);

    u64 accA2[16];
    #pragma unroll
    for (int s = 0; s < 16; s++) accA2[s] = 0ull;

    const int M   = NA;
    const int PPh = (M * (M - 1)) >> 1;   // unordered pairs; ref double-counts -> x2 in wgt
    for (int k = tid; k < PPh; k += TPB) {
        // decode triangular index: k = b(b-1)/2 + a, 0 <= a < b
        int b = (int)(0.5f * (1.0f + sqrtf(8.0f * (float)k + 1.0f)));
        int tb = (b * (b - 1)) >> 1;
        if (k < tb)           { b--; tb = (b * (b - 1)) >> 1; }
        else if (k >= tb + b) { b++; tb = (b * (b - 1)) >> 1; }
        const int a = k - tb;

        const float da = ad[a], db = ad[b];
        const float dot = adx[a] * adx[b] + ady[a] * ady[b] + adz[a] * adz[b];
        const float cth = 0.95f * __fdividef(dot, da * db);      // |cth| <= 0.95
        const float sth = sqrtf(fmaxf(1.0f - cth * cth, 0.0f));  // theta in [0,pi]
        const float wgt = 2.0f * afq[a] * afq[b];
        const float davg = 0.5f * (da + db);

        u64 cth2, sth2;
        PACK2(cth2, cth, cth);
        PACK2(sth2, sth, sth);

        #pragma unroll
        for (int az = 0; az < 4; az++) {
            const float sha = 0.9f + 0.65f * (float)az;
            const float u   = davg - sha;
            const float rad = wgt * __expf(-8.0f * u * u);
            u64 rad2;
            PACK2(rad2, rad, rad);
            #pragma unroll
            for (int p = 0; p < 4; p++) {
                // x = 0.5 + cth*0.5cos(ShfZ) + sth*0.5sin(ShfZ)   (exact identity
                // for 0.5*(1+cos(theta-ShfZ)), theta in [0,pi])
                u64 x, t;
                FMA2(t, sth2, SZ2[p], HALF2);
                FMA2(x, cth2, CZ2[p], t);
                MUL2(x, x, x);   // x^2
                MUL2(x, x, x);   // x^4
                MUL2(x, x, x);   // x^8
                MUL2(x, x, x);   // x^16
                MUL2(x, x, x);   // x^32
                FMA2(accA2[az * 4 + p], rad2, x, accA2[az * 4 + p]);
            }
        }
    }

    // ---------- shared transpose ----------
    #pragma unroll
    for (int m = 0; m < 16; m++) part[tid][m] = accR[m];
    #pragma unroll
    for (int s = 0; s < 16; s++) {
        float lo, hi;
        UNPACK2(lo, hi, accA2[s]);
        part[tid][16 + 2 * s]     = lo;
        part[tid][16 + 2 * s + 1] = hi;
    }
    __syncthreads();

    // ---------- bounded 8-way-ILP column sums ----------
    // only rows tid < NR (radial) / tid < PPh (angular) are nonzero; rows
    // beyond hold stored zeros, so rounding the bound up to 8 is safe.
    if (tid < 48) {
        const int rawB = (tid < 16) ? NR : PPh;
        const int bnd  = (min(rawB, TPB) + 7) & ~7;
        float v0 = 0.f, v1 = 0.f, v2 = 0.f, v3 = 0.f;
        float v4 = 0.f, v5 = 0.f, v6 = 0.f, v7 = 0.f;
        for (int l = 0; l < bnd; l += 8) {
            v0 += part[l + 0][tid];
            v1 += part[l + 1][tid];
            v2 += part[l + 2][tid];
            v3 += part[l + 3][tid];
            v4 += part[l + 4][tid];
            v5 += part[l + 5][tid];
            v6 += part[l + 6][tid];
            v7 += part[l + 7][tid];
        }
        out[i * 48 + tid] = ((v0 + v1) + (v2 + v3)) + ((v4 + v5) + (v6 + v7));
    }
}

extern "C" void kernel_launch(void* const* d_in, const int* in_sizes, int n_in,
                              void* d_out, int out_size) {
    const float* coords  = (const float*)d_in[0];  // [256,3] fp32
    const float* charges = (const float*)d_in[1];  // [256]   fp32
    float* out = (float*)d_out;                    // [256,48] fp32
    aev_kernel<<<NATOMS, TPB>>>(coords, charges, out);
}